// round 2
// baseline (speedup 1.0000x reference)
#include <cuda_runtime.h>
#include <math.h>

// Problem dims (fixed)
#define TQ 128
#define TK 256
#define BB 8
#define HD 512

// Scratch (__device__ globals: allocation-free per harness rules)
__device__ float g_kp[TK*BB*HD];   // k projection, rows r = k*B + b
__device__ float g_qp[TQ*BB*HD];   // q projection (+b1), rows r = q*B + b
__device__ int   g_klist[BB*TK];   // compacted unmasked k indices per b
__device__ int   g_kcnt[BB];
__device__ unsigned char g_maskdec[BB*TK];

// ---------------------------------------------------------------------------
// prep: detect mask dtype (int32 / uint8 / float32) and build compacted
// per-b key lists. Deterministic serial compaction (trivial cost).
// ---------------------------------------------------------------------------
__global__ void prep_kernel(const void* __restrict__ mask) {
    __shared__ int mode_s;
    if (threadIdx.x == 0) {
        const unsigned* w = (const unsigned*)mask;
        int m = 0; // 0 = int32 bool, 1 = uint8 bool, 2 = float bool
        for (int i = 0; i < 512; i++) {   // first 2048 bytes, valid in all cases
            unsigned v = w[i];
            if (v == 0x3f800000u) { m = 2; break; }
            if (v > 1u) m = 1;
        }
        mode_s = m;
    }
    __syncthreads();
    int b = threadIdx.x;
    if (b < BB) {
        int mode = mode_s;
        int cnt = 0;
        for (int k = 0; k < TK; k++) {
            int mk;
            if (mode == 2)      mk = ((const float*)mask)[k*BB + b] != 0.0f;
            else if (mode == 1) mk = ((const unsigned char*)mask)[k*BB + b] != 0;
            else                mk = ((const int*)mask)[k*BB + b] != 0;
            g_maskdec[b*TK + k] = (unsigned char)mk;
            if (!mk) g_klist[b*TK + cnt++] = k;
        }
        g_kcnt[b] = cnt;
    }
}

// ---------------------------------------------------------------------------
// Projection SGEMM: C[M,512] = A[M,512] @ B[512,512] (+ bias), fp32.
// 64x64 tiles, 256 threads, 4x4 register microtile.
// which==0 -> write g_kp, which==1 -> write g_qp.
// ---------------------------------------------------------------------------
__global__ void proj_gemm(const float* __restrict__ A, const float* __restrict__ B,
                          const float* __restrict__ bias, int which) {
    float* C = which ? g_qp : g_kp;
    __shared__ float As[16][64];
    __shared__ float Bs[16][64];
    const int tid = threadIdx.x;
    const int bm = blockIdx.y * 64, bn = blockIdx.x * 64;
    const int ty = tid >> 4, tx = tid & 15;
    const int arow = tid >> 2,  ac4 = (tid & 3) << 2;
    const int brow = tid >> 4,  bc4 = (tid & 15) << 2;
    float acc[4][4] = {};

    for (int k0 = 0; k0 < HD; k0 += 16) {
        float4 av = *(const float4*)(A + (size_t)(bm + arow) * HD + k0 + ac4);
        float4 bv = *(const float4*)(B + (size_t)(k0 + brow) * HD + bn + bc4);
        As[ac4 + 0][arow] = av.x; As[ac4 + 1][arow] = av.y;
        As[ac4 + 2][arow] = av.z; As[ac4 + 3][arow] = av.w;
        *(float4*)&Bs[brow][bc4] = bv;
        __syncthreads();
        #pragma unroll
        for (int k = 0; k < 16; k++) {
            float4 a  = *(const float4*)&As[k][ty << 2];
            float4 bb = *(const float4*)&Bs[k][tx << 2];
            acc[0][0] += a.x*bb.x; acc[0][1] += a.x*bb.y; acc[0][2] += a.x*bb.z; acc[0][3] += a.x*bb.w;
            acc[1][0] += a.y*bb.x; acc[1][1] += a.y*bb.y; acc[1][2] += a.y*bb.z; acc[1][3] += a.y*bb.w;
            acc[2][0] += a.z*bb.x; acc[2][1] += a.z*bb.y; acc[2][2] += a.z*bb.z; acc[2][3] += a.z*bb.w;
            acc[3][0] += a.w*bb.x; acc[3][1] += a.w*bb.y; acc[3][2] += a.w*bb.z; acc[3][3] += a.w*bb.w;
        }
        __syncthreads();
    }
    #pragma unroll
    for (int i = 0; i < 4; i++) {
        const int row = bm + (ty << 2) + i;
        #pragma unroll
        for (int j = 0; j < 4; j++) {
            const int col = bn + (tx << 2) + j;
            float v = acc[i][j];
            if (bias) v += bias[col];
            C[(size_t)row * HD + col] = v;
        }
    }
}

// ---------------------------------------------------------------------------
// Accurate fast tanh: tanh(x) = (e^{2x}-1)/(e^{2x}+1) via MUFU ex2 + rcp.
// Clamped so ex2 never overflows; rel error ~1e-6.
// ---------------------------------------------------------------------------
__device__ __forceinline__ float ftanh(float x) {
    x = fminf(20.0f, fmaxf(-20.0f, x));
    float t, r;
    asm("ex2.approx.f32 %0, %1;" : "=f"(t) : "f"(x * 2.8853900817779268f));
    asm("rcp.approx.f32 %0, %1;" : "=f"(r) : "f"(t + 1.0f));
    return (t - 1.0f) * r;
}

// ---------------------------------------------------------------------------
// Fused score + masked softmax + ant_vec.
// Grid (16 q-tiles, 8 b), 512 threads. Only unmasked keys (compacted) are
// computed; masked keys get att_prob = 0 exactly (= softmax of -inf).
// ---------------------------------------------------------------------------
__global__ void score_kernel(const float* __restrict__ c_key,
                             const float* __restrict__ W2,
                             float* __restrict__ out_av,
                             float* __restrict__ out_ap) {
    extern __shared__ float sm[];
    float* kp_s = sm;                       // 64 * 513 (padded: conflict-free)
    float* qp_s = kp_s + 64 * 513;          // 8 * 512
    float* w2_s = qp_s + 8 * HD;            // 512
    float* sc_s = w2_s + HD;                // 256 * 8 (scores -> probs)
    int*   kl_s = (int*)(sc_s + TK * 8);    // 256

    const int qt  = blockIdx.x, b = blockIdx.y;
    const int tid = threadIdx.x;
    const int cnt = g_kcnt[b];

    // stage qp tile (b1 already folded in), W2, key list
    for (int i = tid; i < 8 * HD; i += 512) {
        int q = i >> 9, h = i & (HD - 1);
        qp_s[i] = g_qp[(size_t)((qt * 8 + q) * BB + b) * HD + h];
    }
    w2_s[tid] = W2[tid];
    if (tid < TK && tid < cnt) kl_s[tid] = g_klist[b * TK + tid];
    __syncthreads();

    // ---- scores over compacted keys ----
    const int q = tid >> 6, j = tid & 63;
    const int ntiles = (cnt + 63) >> 6;
    for (int t = 0; t < ntiles; t++) {
        if (t) __syncthreads();
        const int base = t << 6;
        for (int i = tid; i < 64 * HD; i += 512) {
            int jj = i >> 9, h = i & (HD - 1);
            int ci = base + jj;
            if (ci < cnt)
                kp_s[jj * 513 + h] = g_kp[(size_t)(kl_s[ci] * BB + b) * HD + h];
        }
        __syncthreads();
        const int ci = base + j;
        if (ci < cnt) {
            const float* kr = kp_s + j * 513;
            const float* qr = qp_s + q * HD;
            float acc = 0.0f;
            #pragma unroll 8
            for (int h = 0; h < HD; h++)
                acc += ftanh(kr[h] + qr[h]) * w2_s[h];
            sc_s[ci * 8 + q] = acc;   // b2 is a constant shift: cancels in softmax
        }
    }
    __syncthreads();

    // ---- masked softmax over k (warps 0-7) + zero-fill masked probs (8-15) ----
    const int wid = tid >> 5, lane = tid & 31;
    if (wid < 8) {
        const int qq = wid;
        float m = -1e30f;
        for (int ci = lane; ci < cnt; ci += 32) m = fmaxf(m, sc_s[ci * 8 + qq]);
        #pragma unroll
        for (int o = 16; o; o >>= 1) m = fmaxf(m, __shfl_xor_sync(0xffffffffu, m, o));
        float s = 0.0f;
        for (int ci = lane; ci < cnt; ci += 32) {
            float e = exp2f((sc_s[ci * 8 + qq] - m) * 1.4426950408889634f);
            sc_s[ci * 8 + qq] = e; s += e;
        }
        #pragma unroll
        for (int o = 16; o; o >>= 1) s += __shfl_xor_sync(0xffffffffu, s, o);
        const float inv = 1.0f / s;
        for (int ci = lane; ci < cnt; ci += 32) {
            float p = sc_s[ci * 8 + qq] * inv;
            sc_s[ci * 8 + qq] = p;
            out_ap[(size_t)kl_s[ci] * (TQ * BB) + (qt * 8 + qq) * BB + b] = p;
        }
    } else {
        const int k = (wid - 8) * 32 + lane;   // covers k = 0..255
        if (g_maskdec[b * TK + k]) {
            #pragma unroll
            for (int qq = 0; qq < 8; qq++)
                out_ap[(size_t)k * (TQ * BB) + (qt * 8 + qq) * BB + b] = 0.0f;
        }
    }
    __syncthreads();

    // ---- ant_vec[q,b,h] = sum_k p[k,q] * c_key[k,b,h] ----
    const int h = tid;   // 512 threads == HD
    float a0=0,a1=0,a2=0,a3=0,a4=0,a5=0,a6=0,a7=0;
    #pragma unroll 8
    for (int ci = 0; ci < cnt; ci++) {
        float ck = c_key[(size_t)kl_s[ci] * (BB * HD) + b * HD + h];
        float4 p0 = *(const float4*)&sc_s[ci * 8];
        float4 p1 = *(const float4*)&sc_s[ci * 8 + 4];
        a0 += p0.x * ck; a1 += p0.y * ck; a2 += p0.z * ck; a3 += p0.w * ck;
        a4 += p1.x * ck; a5 += p1.y * ck; a6 += p1.z * ck; a7 += p1.w * ck;
    }
    float av[8] = {a0,a1,a2,a3,a4,a5,a6,a7};
    #pragma unroll
    for (int qq = 0; qq < 8; qq++)
        out_av[(size_t)(qt * 8 + qq) * (BB * HD) + b * HD + h] = av[qq];
}

// ---------------------------------------------------------------------------
extern "C" void kernel_launch(void* const* d_in, const int* in_sizes, int n_in,
                              void* d_out, int out_size) {
    const float* query = (const float*)d_in[0];   // [128,8,512]
    const float* c_key = (const float*)d_in[1];   // [256,8,512]
    const void*  mask  = d_in[2];                 // [256,8] bool-ish
    const float* W1    = (const float*)d_in[3];   // [1024,512]
    const float* b1    = (const float*)d_in[4];   // [512]
    const float* W2    = (const float*)d_in[5];   // [512,1]
    (void)d_in; (void)in_sizes; (void)n_in; (void)out_size;

    float* out    = (float*)d_out;
    float* out_av = out;                          // ant_vec [128,8,512]
    float* out_ap = out + (size_t)TQ * BB * HD;   // att_prob [256,128,8]

    const size_t smem = (size_t)(64 * 513 + 8 * HD + HD + TK * 8) * sizeof(float)
                      + (size_t)TK * sizeof(int);
    cudaFuncSetAttribute(score_kernel, cudaFuncAttributeMaxDynamicSharedMemorySize,
                         (int)smem);

    prep_kernel<<<1, 8>>>(mask);
    proj_gemm<<<dim3(8, (TK * BB) / 64), 256>>>(c_key, W1, nullptr, 0);
    proj_gemm<<<dim3(8, (TQ * BB) / 64), 256>>>(query, W1 + HD * HD, b1, 1);
    score_kernel<<<dim3(TQ / 8, BB), 512, smem>>>(c_key, W2, out_av, out_ap);
}

// round 3
// speedup vs baseline: 1.2063x; 1.2063x over previous
#include <cuda_runtime.h>
#include <cuda_bf16.h>
#include <math.h>

#define TQ 128
#define TK 256
#define BB 8
#define HD 512

// Scratch (__device__ globals: allocation-free per harness rules)
__device__ float g_kp[TK*BB*HD];   // k projection, rows r = k*B + b
__device__ float g_qp[TQ*BB*HD];   // q projection (+b1), rows r = q*B + b
__device__ int   g_klist[BB*TK];   // compacted unmasked k indices per b
__device__ int   g_kcnt[BB];
__device__ unsigned char g_maskdec[BB*TK];

// ---------------------------------------------------------------------------
// prep: detect mask dtype (int32 / uint8 / float32) and build compacted
// per-b key lists.
// ---------------------------------------------------------------------------
__global__ void prep_kernel(const void* __restrict__ mask) {
    __shared__ int mode_s;
    if (threadIdx.x == 0) {
        const unsigned* w = (const unsigned*)mask;
        int m = 0; // 0 = int32, 1 = uint8, 2 = float
        for (int i = 0; i < 512; i++) {
            unsigned v = w[i];
            if (v == 0x3f800000u) { m = 2; break; }
            if (v > 1u) m = 1;
        }
        mode_s = m;
    }
    __syncthreads();
    int b = threadIdx.x;
    if (b < BB) {
        int mode = mode_s;
        int cnt = 0;
        for (int k = 0; k < TK; k++) {
            int mk;
            if (mode == 2)      mk = ((const float*)mask)[k*BB + b] != 0.0f;
            else if (mode == 1) mk = ((const unsigned char*)mask)[k*BB + b] != 0;
            else                mk = ((const int*)mask)[k*BB + b] != 0;
            g_maskdec[b*TK + k] = (unsigned char)mk;
            if (!mk) g_klist[b*TK + cnt++] = k;
        }
        g_kcnt[b] = cnt;
    }
}

// ---------------------------------------------------------------------------
// bf16x2-split tensor-core projection GEMM.
// C[M,512] = A[M,512] @ B[512,512] (+bias).  A,B fp32 in gmem, converted
// in-kernel to (hi,lo) bf16; C = Ah*Bh + Ah*Bl + Al*Bh (AlBl ~2^-16, dropped).
// Block: 64x64 tile, 128 threads (4 warps, each 16 rows x 64 cols).
// ---------------------------------------------------------------------------
#define LDSM4(R, addr) \
    asm volatile("ldmatrix.sync.aligned.m8n8.x4.shared.b16 {%0,%1,%2,%3}, [%4];" \
        : "=r"(R[0]),"=r"(R[1]),"=r"(R[2]),"=r"(R[3]) : "r"(addr))
#define LDSM4T(R, addr) \
    asm volatile("ldmatrix.sync.aligned.m8n8.x4.trans.shared.b16 {%0,%1,%2,%3}, [%4];" \
        : "=r"(R[0]),"=r"(R[1]),"=r"(R[2]),"=r"(R[3]) : "r"(addr))
#define MMA_BF16(C, A, B0, B1) \
    asm volatile("mma.sync.aligned.m16n8k16.row.col.f32.bf16.bf16.f32 " \
        "{%0,%1,%2,%3},{%4,%5,%6,%7},{%8,%9},{%0,%1,%2,%3};" \
        : "+f"(C[0]),"+f"(C[1]),"+f"(C[2]),"+f"(C[3]) \
        : "r"(A[0]),"r"(A[1]),"r"(A[2]),"r"(A[3]), "r"(B0),"r"(B1))

__device__ __forceinline__ void cvt_store_hl(__nv_bfloat16* H, __nv_bfloat16* L,
                                             int idx, float4 v) {
    __nv_bfloat16 hx = __float2bfloat16(v.x), hy = __float2bfloat16(v.y);
    __nv_bfloat16 hz = __float2bfloat16(v.z), hw = __float2bfloat16(v.w);
    __nv_bfloat16 lx = __float2bfloat16(v.x - __bfloat162float(hx));
    __nv_bfloat16 ly = __float2bfloat16(v.y - __bfloat162float(hy));
    __nv_bfloat16 lz = __float2bfloat16(v.z - __bfloat162float(hz));
    __nv_bfloat16 lw = __float2bfloat16(v.w - __bfloat162float(hw));
    *(__nv_bfloat162*)&H[idx]   = __nv_bfloat162(hx, hy);
    *(__nv_bfloat162*)&H[idx+2] = __nv_bfloat162(hz, hw);
    *(__nv_bfloat162*)&L[idx]   = __nv_bfloat162(lx, ly);
    *(__nv_bfloat162*)&L[idx+2] = __nv_bfloat162(lz, lw);
}

__global__ void proj_mma(const float* __restrict__ A, const float* __restrict__ Bsrc,
                         const float* __restrict__ bias, int which) {
    float* C = which ? g_qp : g_kp;
    __shared__ __align__(16) __nv_bfloat16 Ahs[64*72], Als[64*72];
    __shared__ __align__(16) __nv_bfloat16 Bhs[64*72], Bls[64*72];
    const int tid = threadIdx.x, w = tid >> 5, l = tid & 31;
    const int bm = blockIdx.y * 64, bn = blockIdx.x * 64;
    const int lr = tid >> 1, lc0 = (tid & 1) * 32;
    float acc[8][4] = {};

    for (int kc = 0; kc < HD; kc += 64) {
        const float* Ap = A    + (size_t)(bm + lr) * HD + kc + lc0;
        const float* Bp = Bsrc + (size_t)(kc + lr) * HD + bn + lc0;
        #pragma unroll
        for (int i = 0; i < 8; i++) {
            cvt_store_hl(Ahs, Als, lr*72 + lc0 + i*4, *(const float4*)(Ap + i*4));
            cvt_store_hl(Bhs, Bls, lr*72 + lc0 + i*4, *(const float4*)(Bp + i*4));
        }
        __syncthreads();
        #pragma unroll
        for (int ks = 0; ks < 4; ks++) {
            const int k0 = ks * 16;
            unsigned aoff = (unsigned)(((16*w + (l & 15)) * 72 + k0 + (l >> 4)*8) * 2);
            unsigned ah_a = (unsigned)__cvta_generic_to_shared(Ahs) + aoff;
            unsigned al_a = (unsigned)__cvta_generic_to_shared(Als) + aoff;
            unsigned ah[4], al[4];
            LDSM4(ah, ah_a); LDSM4(al, al_a);
            #pragma unroll
            for (int nt = 0; nt < 4; nt++) {
                const int n0 = nt * 16;
                unsigned boff = (unsigned)(((k0 + (l & 15)) * 72 + n0 + (l >> 4)*8) * 2);
                unsigned bh_a = (unsigned)__cvta_generic_to_shared(Bhs) + boff;
                unsigned bl_a = (unsigned)__cvta_generic_to_shared(Bls) + boff;
                unsigned bh[4], bl[4];
                LDSM4T(bh, bh_a); LDSM4T(bl, bl_a);
                MMA_BF16(acc[2*nt],   ah, bh[0], bh[1]);
                MMA_BF16(acc[2*nt],   ah, bl[0], bl[1]);
                MMA_BF16(acc[2*nt],   al, bh[0], bh[1]);
                MMA_BF16(acc[2*nt+1], ah, bh[2], bh[3]);
                MMA_BF16(acc[2*nt+1], ah, bl[2], bl[3]);
                MMA_BF16(acc[2*nt+1], al, bh[2], bh[3]);
            }
        }
        __syncthreads();
    }
    const int g = l >> 2, tig = l & 3;
    const int row = bm + 16*w + g;
    #pragma unroll
    for (int t = 0; t < 8; t++) {
        const int col = bn + t*8 + tig*2;
        float b0 = 0.f, b1v = 0.f;
        if (bias) { b0 = bias[col]; b1v = bias[col+1]; }
        C[(size_t)row * HD + col]         = acc[t][0] + b0;
        C[(size_t)row * HD + col + 1]     = acc[t][1] + b1v;
        C[(size_t)(row+8) * HD + col]     = acc[t][2] + b0;
        C[(size_t)(row+8) * HD + col + 1] = acc[t][3] + b1v;
    }
}

// ---------------------------------------------------------------------------
// MUFU tanh (abs err ~5e-4; score error ~2.5e-4 after dot with W2)
// ---------------------------------------------------------------------------
__device__ __forceinline__ float tanha(float x) {
    float y;
    asm("tanh.approx.f32 %0, %1;" : "=f"(y) : "f"(x));
    return y;
}

// ---------------------------------------------------------------------------
// Fused score + masked softmax + ant_vec.  Grid (16 q-tiles, 8 b), 512 thr.
// kp read straight from gmem through L1 (float4); qp/W2 broadcast via smem.
// ---------------------------------------------------------------------------
__global__ void score_kernel(const float* __restrict__ c_key,
                             const float* __restrict__ W2,
                             float* __restrict__ out_av,
                             float* __restrict__ out_ap) {
    extern __shared__ float sm[];
    float* qp_s = sm;                     // 8*512
    float* w2_s = qp_s + 8*HD;            // 512
    float* sc_s = w2_s + HD;              // 256*8
    int*   kl_s = (int*)(sc_s + TK*8);    // 256

    const int qt = blockIdx.x, b = blockIdx.y;
    const int tid = threadIdx.x;
    const int cnt = g_kcnt[b];

    {
        float4* qp4 = (float4*)qp_s;
        #pragma unroll
        for (int i = tid; i < 8*HD/4; i += 512) {
            int qq = i >> 7, h4 = i & 127;
            qp4[i] = *(const float4*)(g_qp + (size_t)((qt*8 + qq)*BB + b)*HD + h4*4);
        }
        if (tid < 128) ((float4*)w2_s)[tid] = *(const float4*)(W2 + tid*4);
        if (tid < TK) kl_s[tid] = (tid < cnt) ? g_klist[b*TK + tid] : 0;
    }
    __syncthreads();

    // ---- scores over compacted keys ----
    const int q = tid >> 6, j = tid & 63;
    const float4* qr = (const float4*)(qp_s + q*HD);
    const float4* w4 = (const float4*)w2_s;
    for (int ci = j; ci < cnt; ci += 64) {
        const float4* kr = (const float4*)(g_kp + (size_t)(kl_s[ci]*BB + b)*HD);
        float acc0 = 0.f, acc1 = 0.f;
        #pragma unroll 8
        for (int h4 = 0; h4 < 128; h4++) {
            float4 kv = kr[h4];
            float4 qv = qr[h4];
            float4 wv = w4[h4];
            acc0 += tanha(kv.x + qv.x)*wv.x + tanha(kv.z + qv.z)*wv.z;
            acc1 += tanha(kv.y + qv.y)*wv.y + tanha(kv.w + qv.w)*wv.w;
        }
        sc_s[ci*8 + q] = acc0 + acc1;   // b2 shift cancels in softmax
    }
    __syncthreads();

    // ---- masked softmax over k (warps 0-7) + zero-fill masked (warps 8-15) ----
    const int wid = tid >> 5, lane = tid & 31;
    if (wid < 8) {
        const int qq = wid;
        float m = -1e30f;
        for (int ci = lane; ci < cnt; ci += 32) m = fmaxf(m, sc_s[ci*8 + qq]);
        #pragma unroll
        for (int o = 16; o; o >>= 1) m = fmaxf(m, __shfl_xor_sync(0xffffffffu, m, o));
        float s = 0.f;
        for (int ci = lane; ci < cnt; ci += 32) {
            float e = exp2f((sc_s[ci*8 + qq] - m) * 1.4426950408889634f);
            sc_s[ci*8 + qq] = e; s += e;
        }
        #pragma unroll
        for (int o = 16; o; o >>= 1) s += __shfl_xor_sync(0xffffffffu, s, o);
        const float inv = 1.0f / s;
        for (int ci = lane; ci < cnt; ci += 32) {
            float p = sc_s[ci*8 + qq] * inv;
            sc_s[ci*8 + qq] = p;
            out_ap[(size_t)kl_s[ci]*(TQ*BB) + (qt*8 + qq)*BB + b] = p;
        }
    } else {
        const int k = (wid - 8)*32 + lane;
        if (g_maskdec[b*TK + k]) {
            #pragma unroll
            for (int qq = 0; qq < 8; qq++)
                out_ap[(size_t)k*(TQ*BB) + (qt*8 + qq)*BB + b] = 0.0f;
        }
    }
    __syncthreads();

    // ---- ant_vec[q,b,h] = sum_k p[k,q] * c_key[k,b,h] ----
    const int h = tid;
    float a0=0,a1=0,a2=0,a3=0,a4=0,a5=0,a6=0,a7=0;
    #pragma unroll 8
    for (int ci = 0; ci < cnt; ci++) {
        float ck = c_key[(size_t)kl_s[ci]*(BB*HD) + b*HD + h];
        float4 p0 = *(const float4*)&sc_s[ci*8];
        float4 p1 = *(const float4*)&sc_s[ci*8 + 4];
        a0 += p0.x*ck; a1 += p0.y*ck; a2 += p0.z*ck; a3 += p0.w*ck;
        a4 += p1.x*ck; a5 += p1.y*ck; a6 += p1.z*ck; a7 += p1.w*ck;
    }
    float av[8] = {a0,a1,a2,a3,a4,a5,a6,a7};
    #pragma unroll
    for (int qq = 0; qq < 8; qq++)
        out_av[(size_t)(qt*8 + qq)*(BB*HD) + b*HD + h] = av[qq];
}

// ---------------------------------------------------------------------------
extern "C" void kernel_launch(void* const* d_in, const int* in_sizes, int n_in,
                              void* d_out, int out_size) {
    const float* query = (const float*)d_in[0];   // [128,8,512]
    const float* c_key = (const float*)d_in[1];   // [256,8,512]
    const void*  mask  = d_in[2];                 // [256,8] bool-ish
    const float* W1    = (const float*)d_in[3];   // [1024,512]
    const float* b1    = (const float*)d_in[4];   // [512]
    const float* W2    = (const float*)d_in[5];   // [512,1]
    (void)in_sizes; (void)n_in; (void)out_size;

    float* out    = (float*)d_out;
    float* out_av = out;                          // ant_vec [128,8,512]
    float* out_ap = out + (size_t)TQ*BB*HD;       // att_prob [256,128,8]

    const size_t smem = (size_t)(8*HD + HD + TK*8) * sizeof(float)
                      + (size_t)TK * sizeof(int);   // ~27.5 KB

    prep_kernel<<<1, 8>>>(mask);
    proj_mma<<<dim3(8, (TK*BB)/64), 128>>>(c_key, W1, nullptr, 0);
    proj_mma<<<dim3(8, (TQ*BB)/64), 128>>>(query, W1 + HD*HD, b1, 1);
    score_kernel<<<dim3(TQ/8, BB), 512, smem>>>(c_key, W2, out_av, out_ap);
}

// round 5
// speedup vs baseline: 2.2093x; 1.8315x over previous
#include <cuda_runtime.h>
#include <cuda_bf16.h>
#include <math.h>

#define TQ 128
#define TK 256
#define BB 8
#define HD 512

// rows: 0..2047 = c_key (k*8+b), 2048..3071 = query (q*8+b)
#define XROWS (TK*BB + TQ*BB)

__device__ float g_kp[TK*BB*HD];
__device__ float g_qp[TQ*BB*HD];
__device__ int   g_klist[BB*TK];
__device__ int   g_kcnt[BB];
__device__ unsigned char g_maskdec[BB*TK];
__device__ __align__(16) __nv_bfloat16 g_xh[XROWS*HD];
__device__ __align__(16) __nv_bfloat16 g_xl[XROWS*HD];
__device__ __align__(16) __nv_bfloat16 g_wh[2*HD*HD];
__device__ __align__(16) __nv_bfloat16 g_wl[2*HD*HD];

__device__ __forceinline__ unsigned pack_bf2(__nv_bfloat16 a, __nv_bfloat16 b) {
    __nv_bfloat162 t(a, b);
    return *(unsigned*)&t;
}

// ---------------------------------------------------------------------------
// convert: fp32 -> bf16 hi/lo split for c_key, query, W1.  Block 0 also does
// mask decode + per-b key compaction.
// ---------------------------------------------------------------------------
__global__ void __launch_bounds__(256) convert_kernel(
        const float* __restrict__ query,
        const float* __restrict__ c_key,
        const float* __restrict__ W1,
        const void* __restrict__ mask) {
    if (blockIdx.x == 0 && threadIdx.x < 8) {
        const unsigned* w = (const unsigned*)mask;
        int mode = 0; // 0 int32, 1 uint8, 2 float
        for (int i = 0; i < 512; i++) {
            unsigned v = w[i];
            if (v == 0x3f800000u) { mode = 2; break; }
            if (v > 1u) mode = 1;
        }
        int b = threadIdx.x, cnt = 0;
        for (int k = 0; k < TK; k++) {
            int mk;
            if (mode == 2)      mk = ((const float*)mask)[k*BB + b] != 0.0f;
            else if (mode == 1) mk = ((const unsigned char*)mask)[k*BB + b] != 0;
            else                mk = ((const int*)mask)[k*BB + b] != 0;
            g_maskdec[b*TK + k] = (unsigned char)mk;
            if (!mk) g_klist[b*TK + cnt++] = k;
        }
        g_kcnt[b] = cnt;
    }

    const int NCK = (TK*BB*HD)/4;      // 262144 float4
    const int NQ  = (TQ*BB*HD)/4;      // 131072
    const int NW  = (2*HD*HD)/4;       // 131072
    const int total = NCK + NQ + NW;
    const int stride = gridDim.x * blockDim.x;
    for (int i = blockIdx.x*blockDim.x + threadIdx.x; i < total; i += stride) {
        const float4* src; __nv_bfloat16 *H, *L; int e;
        if (i < NCK)          { src = (const float4*)c_key + i;       e = i*4;                  H = g_xh; L = g_xl; }
        else if (i < NCK+NQ)  { src = (const float4*)query + (i-NCK); e = (i-NCK)*4 + TK*BB*HD; H = g_xh; L = g_xl; }
        else                  { src = (const float4*)W1 + (i-NCK-NQ); e = (i-NCK-NQ)*4;         H = g_wh; L = g_wl; }
        float4 v = *src;
        __nv_bfloat16 hx = __float2bfloat16(v.x), hy = __float2bfloat16(v.y);
        __nv_bfloat16 hz = __float2bfloat16(v.z), hw = __float2bfloat16(v.w);
        __nv_bfloat16 lx = __float2bfloat16(v.x - __bfloat162float(hx));
        __nv_bfloat16 ly = __float2bfloat16(v.y - __bfloat162float(hy));
        __nv_bfloat16 lz = __float2bfloat16(v.z - __bfloat162float(hz));
        __nv_bfloat16 lw = __float2bfloat16(v.w - __bfloat162float(hw));
        uint2 hp = make_uint2(pack_bf2(hx,hy), pack_bf2(hz,hw));
        uint2 lp = make_uint2(pack_bf2(lx,ly), pack_bf2(lz,lw));
        *(uint2*)&H[e] = hp;
        *(uint2*)&L[e] = lp;
    }
}

// ---------------------------------------------------------------------------
// Projection GEMM (bf16 hi/lo split, 3 MMA products).  128x64 tile, 256 thr.
// grid.y: 0..15 -> K-proj (rows of c_key), 16..23 -> Q-proj (+bias b1).
// XOR-swizzled smem (8-elem chunks), conflict-free ldmatrix.
// ---------------------------------------------------------------------------
#define LDSM4(R, addr) \
    asm volatile("ldmatrix.sync.aligned.m8n8.x4.shared.b16 {%0,%1,%2,%3}, [%4];" \
        : "=r"(R[0]),"=r"(R[1]),"=r"(R[2]),"=r"(R[3]) : "r"(addr))
#define LDSM4T(R, addr) \
    asm volatile("ldmatrix.sync.aligned.m8n8.x4.trans.shared.b16 {%0,%1,%2,%3}, [%4];" \
        : "=r"(R[0]),"=r"(R[1]),"=r"(R[2]),"=r"(R[3]) : "r"(addr))
#define MMA_BF16(C, A, B0, B1) \
    asm volatile("mma.sync.aligned.m16n8k16.row.col.f32.bf16.bf16.f32 " \
        "{%0,%1,%2,%3},{%4,%5,%6,%7},{%8,%9},{%0,%1,%2,%3};" \
        : "+f"(C[0]),"+f"(C[1]),"+f"(C[2]),"+f"(C[3]) \
        : "r"(A[0]),"r"(A[1]),"r"(A[2]),"r"(A[3]), "r"(B0),"r"(B1))

__global__ void __launch_bounds__(256) proj_mma(const float* __restrict__ b1) {
    __shared__ __align__(16) __nv_bfloat16 Ah[128*64], Al[128*64];
    __shared__ __align__(16) __nv_bfloat16 Bh[64*64],  Bl[64*64];
    const int tid = threadIdx.x, w = tid >> 5, l = tid & 31;
    const int by = blockIdx.y, bn = blockIdx.x * 64;
    const int isQ = (by >= 16);
    const int xrow0 = isQ ? (TK*BB + (by-16)*128) : by*128;
    const int wrow0 = isQ ? HD : 0;
    float* C = isQ ? g_qp : g_kp;
    const int crow0 = isQ ? (by-16)*128 : by*128;
    float acc[8][4] = {};

    for (int kc = 0; kc < HD; kc += 64) {
        #pragma unroll
        for (int t = 0; t < 4; t++) {
            int idx = tid + t*256;
            int r = idx >> 3, c = idx & 7;
            int so = r*64 + ((c ^ (r & 7)) << 3);
            size_t ge = (size_t)(xrow0 + r)*HD + kc + c*8;
            *(uint4*)&Ah[so] = *(const uint4*)&g_xh[ge];
            *(uint4*)&Al[so] = *(const uint4*)&g_xl[ge];
        }
        #pragma unroll
        for (int t = 0; t < 2; t++) {
            int idx = tid + t*256;
            int r = idx >> 3, c = idx & 7;
            int so = r*64 + ((c ^ (r & 7)) << 3);
            size_t ge = (size_t)(wrow0 + kc + r)*HD + bn + c*8;
            *(uint4*)&Bh[so] = *(const uint4*)&g_wh[ge];
            *(uint4*)&Bl[so] = *(const uint4*)&g_wl[ge];
        }
        __syncthreads();
        #pragma unroll
        for (int ks = 0; ks < 4; ks++) {
            int arow = 16*w + (l & 15);
            int ac = ks*2 + (l >> 4);
            unsigned aoff = (unsigned)((arow*64 + ((ac ^ (arow & 7)) << 3)) * 2);
            unsigned ah_a = (unsigned)__cvta_generic_to_shared(Ah) + aoff;
            unsigned al_a = (unsigned)__cvta_generic_to_shared(Al) + aoff;
            unsigned ah[4], al[4];
            LDSM4(ah, ah_a); LDSM4(al, al_a);
            #pragma unroll
            for (int nt = 0; nt < 4; nt++) {
                int brow = ks*16 + (l & 15);
                int bc = nt*2 + (l >> 4);
                unsigned boff = (unsigned)((brow*64 + ((bc ^ (brow & 7)) << 3)) * 2);
                unsigned bh_a = (unsigned)__cvta_generic_to_shared(Bh) + boff;
                unsigned bl_a = (unsigned)__cvta_generic_to_shared(Bl) + boff;
                unsigned bh[4], bl[4];
                LDSM4T(bh, bh_a); LDSM4T(bl, bl_a);
                MMA_BF16(acc[2*nt],   ah, bh[0], bh[1]);
                MMA_BF16(acc[2*nt],   ah, bl[0], bl[1]);
                MMA_BF16(acc[2*nt],   al, bh[0], bh[1]);
                MMA_BF16(acc[2*nt+1], ah, bh[2], bh[3]);
                MMA_BF16(acc[2*nt+1], ah, bl[2], bl[3]);
                MMA_BF16(acc[2*nt+1], al, bh[2], bh[3]);
            }
        }
        __syncthreads();
    }
    const int g = l >> 2, tig = l & 3;
    const int row = crow0 + 16*w + g;
    #pragma unroll
    for (int t = 0; t < 8; t++) {
        const int col = bn + t*8 + tig*2;
        float v0 = 0.f, v1 = 0.f;
        if (isQ) { v0 = b1[col]; v1 = b1[col+1]; }
        C[(size_t)row*HD + col]       = acc[t][0] + v0;
        C[(size_t)row*HD + col+1]     = acc[t][1] + v1;
        C[(size_t)(row+8)*HD + col]   = acc[t][2] + v0;
        C[(size_t)(row+8)*HD + col+1] = acc[t][3] + v1;
    }
}

// ---------------------------------------------------------------------------
__device__ __forceinline__ float tanha(float x) {
    float y;
    asm("tanh.approx.f32 %0, %1;" : "=f"(y) : "f"(x));
    return y;
}

// ---------------------------------------------------------------------------
// Fused score + masked softmax + ant_vec.  Grid (16 q-tiles, 8 b), 512 thr.
// Warp per key; lanes span h (coalesced kv LDG, conflict-free qv/wv LDS).
// __launch_bounds__(512,1) caps regs at 128 so the launch fits.
// ---------------------------------------------------------------------------
__global__ void __launch_bounds__(512, 1) score_kernel(
        const float* __restrict__ c_key,
        const float* __restrict__ W2,
        float* __restrict__ out_av,
        float* __restrict__ out_ap) {
    __shared__ float qp_s[8*HD];
    __shared__ float w2_s[HD];
    __shared__ float sc_s[TK*8];
    __shared__ int   kl_s[TK];

    const int qt = blockIdx.x, b = blockIdx.y;
    const int tid = threadIdx.x;
    const int cnt = g_kcnt[b];
    const int wid = tid >> 5, lane = tid & 31;

    {
        float4* qp4 = (float4*)qp_s;
        #pragma unroll
        for (int i = tid; i < 8*HD/4; i += 512) {
            int qq = i >> 7, h4 = i & 127;
            qp4[i] = *(const float4*)(g_qp + (size_t)((qt*8 + qq)*BB + b)*HD + h4*4);
        }
        if (tid < 128) ((float4*)w2_s)[tid] = *(const float4*)(W2 + tid*4);
        if (tid < TK) kl_s[tid] = (tid < cnt) ? g_klist[b*TK + tid] : 0;
    }
    __syncthreads();

    // ---- scores: warp j handles keys ci = j, j+16, ... ----
    const float4* qp4 = (const float4*)qp_s;
    float4 wv[4];
    #pragma unroll
    for (int i = 0; i < 4; i++) wv[i] = ((const float4*)w2_s)[lane + 32*i];

    for (int ci = wid; ci < cnt; ci += 16) {
        const float4* kr = (const float4*)(g_kp + (size_t)(kl_s[ci]*BB + b)*HD);
        float acc[8] = {};
        #pragma unroll
        for (int i = 0; i < 4; i++) {
            float4 kv = kr[lane + 32*i];
            #pragma unroll
            for (int q = 0; q < 8; q++) {
                float4 qv = qp4[q*128 + lane + 32*i];
                acc[q] += tanha(kv.x+qv.x)*wv[i].x + tanha(kv.y+qv.y)*wv[i].y
                        + tanha(kv.z+qv.z)*wv[i].z + tanha(kv.w+qv.w)*wv[i].w;
            }
        }
        #pragma unroll
        for (int q = 0; q < 8; q++) {
            #pragma unroll
            for (int o = 16; o; o >>= 1)
                acc[q] += __shfl_xor_sync(0xffffffffu, acc[q], o);
        }
        if (lane == 0) {
            *(float4*)&sc_s[ci*8]     = make_float4(acc[0], acc[1], acc[2], acc[3]);
            *(float4*)&sc_s[ci*8 + 4] = make_float4(acc[4], acc[5], acc[6], acc[7]);
        }
    }
    __syncthreads();

    // ---- masked softmax over k (warps 0-7) + zero-fill masked (warps 8-15) --
    if (wid < 8) {
        const int qq = wid;
        float m = -1e30f;
        for (int ci = lane; ci < cnt; ci += 32) m = fmaxf(m, sc_s[ci*8 + qq]);
        #pragma unroll
        for (int o = 16; o; o >>= 1) m = fmaxf(m, __shfl_xor_sync(0xffffffffu, m, o));
        float s = 0.f;
        for (int ci = lane; ci < cnt; ci += 32) {
            float e = exp2f((sc_s[ci*8 + qq] - m) * 1.4426950408889634f);
            sc_s[ci*8 + qq] = e; s += e;
        }
        #pragma unroll
        for (int o = 16; o; o >>= 1) s += __shfl_xor_sync(0xffffffffu, s, o);
        const float inv = 1.0f / s;
        for (int ci = lane; ci < cnt; ci += 32) {
            float p = sc_s[ci*8 + qq] * inv;
            sc_s[ci*8 + qq] = p;
            out_ap[(size_t)kl_s[ci]*(TQ*BB) + (qt*8 + qq)*BB + b] = p;
        }
    } else {
        const int k = (wid - 8)*32 + lane;
        if (g_maskdec[b*TK + k]) {
            #pragma unroll
            for (int qq = 0; qq < 8; qq++)
                out_ap[(size_t)k*(TQ*BB) + (qt*8 + qq)*BB + b] = 0.0f;
        }
    }
    __syncthreads();

    // ---- ant_vec[q,b,h] = sum_k p[k,q] * c_key[k,b,h] ----
    const int h = tid;
    float a0=0,a1=0,a2=0,a3=0,a4=0,a5=0,a6=0,a7=0;
    #pragma unroll 8
    for (int ci = 0; ci < cnt; ci++) {
        float ck = c_key[(size_t)kl_s[ci]*(BB*HD) + b*HD + h];
        float4 p0 = *(const float4*)&sc_s[ci*8];
        float4 p1 = *(const float4*)&sc_s[ci*8 + 4];
        a0 += p0.x*ck; a1 += p0.y*ck; a2 += p0.z*ck; a3 += p0.w*ck;
        a4 += p1.x*ck; a5 += p1.y*ck; a6 += p1.z*ck; a7 += p1.w*ck;
    }
    float av[8] = {a0,a1,a2,a3,a4,a5,a6,a7};
    #pragma unroll
    for (int qq = 0; qq < 8; qq++)
        out_av[(size_t)(qt*8 + qq)*(BB*HD) + b*HD + h] = av[qq];
}

// ---------------------------------------------------------------------------
extern "C" void kernel_launch(void* const* d_in, const int* in_sizes, int n_in,
                              void* d_out, int out_size) {
    const float* query = (const float*)d_in[0];
    const float* c_key = (const float*)d_in[1];
    const void*  mask  = d_in[2];
    const float* W1    = (const float*)d_in[3];
    const float* b1    = (const float*)d_in[4];
    const float* W2    = (const float*)d_in[5];
    (void)in_sizes; (void)n_in; (void)out_size;

    float* out    = (float*)d_out;
    float* out_av = out;
    float* out_ap = out + (size_t)TQ*BB*HD;

    convert_kernel<<<512, 256>>>(query, c_key, W1, mask);
    proj_mma<<<dim3(8, 24), 256>>>(b1);
    score_kernel<<<dim3(TQ/8, BB), 512>>>(c_key, W2, out_av, out_ap);
}

// round 7
// speedup vs baseline: 2.9083x; 1.3164x over previous
#include <cuda_runtime.h>
#include <cuda_bf16.h>
#include <math.h>

#define TQ 128
#define TK 256
#define BB 8
#define HD 512

// rows: 0..2047 = c_key (k*8+b), 2048..3071 = query (q*8+b)
#define XROWS (TK*BB + TQ*BB)

__device__ float g_kp[TK*BB*HD];
__device__ float g_qp[TQ*BB*HD];
__device__ int   g_klist[BB*TK];
__device__ int   g_kcnt[BB];
__device__ unsigned char g_maskdec[BB*TK];
__device__ __align__(16) __nv_bfloat16 g_xh[XROWS*HD];
__device__ __align__(16) __nv_bfloat16 g_xl[XROWS*HD];
__device__ __align__(16) __nv_bfloat16 g_wh[2*HD*HD];
__device__ __align__(16) __nv_bfloat16 g_wl[2*HD*HD];

__device__ __forceinline__ unsigned pack_bf2(__nv_bfloat16 a, __nv_bfloat16 b) {
    __nv_bfloat162 t(a, b);
    return *(unsigned*)&t;
}

// ---------------------------------------------------------------------------
// mask_prep: parallel mask-dtype detect + per-b order-preserving compaction.
// 1 block, 256 threads.  Warp w handles b = w via ballot prefix-sums.
// ---------------------------------------------------------------------------
__global__ void __launch_bounds__(256) mask_prep(const void* __restrict__ mask) {
    __shared__ int s_isfloat, s_isbig;
    const int tid = threadIdx.x;
    if (tid == 0) { s_isfloat = 0; s_isbig = 0; }
    __syncthreads();
    // first 2048 bytes are valid for all candidate dtypes
    for (int i = tid; i < 512; i += 256) {
        unsigned v = ((const unsigned*)mask)[i];
        if (v == 0x3f800000u) s_isfloat = 1;
        else if (v > 1u)      s_isbig = 1;
    }
    __syncthreads();
    const int mode = s_isfloat ? 2 : (s_isbig ? 1 : 0);
    const int w = tid >> 5, lane = tid & 31;
    if (w < BB) {
        const int b = w;
        int base = 0;
        #pragma unroll
        for (int c = 0; c < 8; c++) {
            const int k = c * 32 + lane;
            int mk;
            if (mode == 2)      mk = ((const float*)mask)[k*BB + b] != 0.0f;
            else if (mode == 1) mk = ((const unsigned char*)mask)[k*BB + b] != 0;
            else                mk = ((const int*)mask)[k*BB + b] != 0;
            g_maskdec[b*TK + k] = (unsigned char)mk;
            unsigned bal = __ballot_sync(0xffffffffu, !mk);
            if (!mk) {
                int pos = base + __popc(bal & ((1u << lane) - 1u));
                g_klist[b*TK + pos] = k;
            }
            base += __popc(bal);
        }
        if (lane == 0) g_kcnt[b] = base;
    }
}

// ---------------------------------------------------------------------------
// convert: pure streaming fp32 -> bf16 hi/lo split for c_key, query, W1.
// ---------------------------------------------------------------------------
__global__ void __launch_bounds__(256) convert_kernel(
        const float* __restrict__ query,
        const float* __restrict__ c_key,
        const float* __restrict__ W1) {
    const int NCK = (TK*BB*HD)/4;      // 262144 float4
    const int NQ  = (TQ*BB*HD)/4;      // 131072
    const int NW  = (2*HD*HD)/4;       // 131072
    const int total = NCK + NQ + NW;
    const int stride = gridDim.x * blockDim.x;
    for (int i = blockIdx.x*blockDim.x + threadIdx.x; i < total; i += stride) {
        const float4* src; __nv_bfloat16 *H, *L; int e;
        if (i < NCK)          { src = (const float4*)c_key + i;       e = i*4;                  H = g_xh; L = g_xl; }
        else if (i < NCK+NQ)  { src = (const float4*)query + (i-NCK); e = (i-NCK)*4 + TK*BB*HD; H = g_xh; L = g_xl; }
        else                  { src = (const float4*)W1 + (i-NCK-NQ); e = (i-NCK-NQ)*4;         H = g_wh; L = g_wl; }
        float4 v = *src;
        __nv_bfloat16 hx = __float2bfloat16(v.x), hy = __float2bfloat16(v.y);
        __nv_bfloat16 hz = __float2bfloat16(v.z), hw = __float2bfloat16(v.w);
        __nv_bfloat16 lx = __float2bfloat16(v.x - __bfloat162float(hx));
        __nv_bfloat16 ly = __float2bfloat16(v.y - __bfloat162float(hy));
        __nv_bfloat16 lz = __float2bfloat16(v.z - __bfloat162float(hz));
        __nv_bfloat16 lw = __float2bfloat16(v.w - __bfloat162float(hw));
        uint2 hp = make_uint2(pack_bf2(hx,hy), pack_bf2(hz,hw));
        uint2 lp = make_uint2(pack_bf2(lx,ly), pack_bf2(lz,lw));
        *(uint2*)&H[e] = hp;
        *(uint2*)&L[e] = lp;
    }
}

// ---------------------------------------------------------------------------
// Projection GEMM (bf16 hi/lo split, 3 MMA products).  128x64 tile, 256 thr.
// grid.y: 0..15 -> K-proj (rows of c_key), 16..23 -> Q-proj (+bias b1).
// XOR-swizzled smem (8-elem chunks), conflict-free ldmatrix.
// ---------------------------------------------------------------------------
#define LDSM4(R, addr) \
    asm volatile("ldmatrix.sync.aligned.m8n8.x4.shared.b16 {%0,%1,%2,%3}, [%4];" \
        : "=r"(R[0]),"=r"(R[1]),"=r"(R[2]),"=r"(R[3]) : "r"(addr))
#define LDSM4T(R, addr) \
    asm volatile("ldmatrix.sync.aligned.m8n8.x4.trans.shared.b16 {%0,%1,%2,%3}, [%4];" \
        : "=r"(R[0]),"=r"(R[1]),"=r"(R[2]),"=r"(R[3]) : "r"(addr))
#define MMA_BF16(C, A, B0, B1) \
    asm volatile("mma.sync.aligned.m16n8k16.row.col.f32.bf16.bf16.f32 " \
        "{%0,%1,%2,%3},{%4,%5,%6,%7},{%8,%9},{%0,%1,%2,%3};" \
        : "+f"(C[0]),"+f"(C[1]),"+f"(C[2]),"+f"(C[3]) \
        : "r"(A[0]),"r"(A[1]),"r"(A[2]),"r"(A[3]), "r"(B0),"r"(B1))

__global__ void __launch_bounds__(256) proj_mma(const float* __restrict__ b1) {
    __shared__ __align__(16) __nv_bfloat16 Ah[128*64], Al[128*64];
    __shared__ __align__(16) __nv_bfloat16 Bh[64*64],  Bl[64*64];
    const int tid = threadIdx.x, w = tid >> 5, l = tid & 31;
    const int by = blockIdx.y, bn = blockIdx.x * 64;
    const int isQ = (by >= 16);
    const int xrow0 = isQ ? (TK*BB + (by-16)*128) : by*128;
    const int wrow0 = isQ ? HD : 0;
    float* C = isQ ? g_qp : g_kp;
    const int crow0 = isQ ? (by-16)*128 : by*128;
    float acc[8][4] = {};

    for (int kc = 0; kc < HD; kc += 64) {
        #pragma unroll
        for (int t = 0; t < 4; t++) {
            int idx = tid + t*256;
            int r = idx >> 3, c = idx & 7;
            int so = r*64 + ((c ^ (r & 7)) << 3);
            size_t ge = (size_t)(xrow0 + r)*HD + kc + c*8;
            *(uint4*)&Ah[so] = *(const uint4*)&g_xh[ge];
            *(uint4*)&Al[so] = *(const uint4*)&g_xl[ge];
        }
        #pragma unroll
        for (int t = 0; t < 2; t++) {
            int idx = tid + t*256;
            int r = idx >> 3, c = idx & 7;
            int so = r*64 + ((c ^ (r & 7)) << 3);
            size_t ge = (size_t)(wrow0 + kc + r)*HD + bn + c*8;
            *(uint4*)&Bh[so] = *(const uint4*)&g_wh[ge];
            *(uint4*)&Bl[so] = *(const uint4*)&g_wl[ge];
        }
        __syncthreads();
        #pragma unroll
        for (int ks = 0; ks < 4; ks++) {
            int arow = 16*w + (l & 15);
            int ac = ks*2 + (l >> 4);
            unsigned aoff = (unsigned)((arow*64 + ((ac ^ (arow & 7)) << 3)) * 2);
            unsigned ah_a = (unsigned)__cvta_generic_to_shared(Ah) + aoff;
            unsigned al_a = (unsigned)__cvta_generic_to_shared(Al) + aoff;
            unsigned ah[4], al[4];
            LDSM4(ah, ah_a); LDSM4(al, al_a);
            #pragma unroll
            for (int nt = 0; nt < 4; nt++) {
                int brow = ks*16 + (l & 15);
                int bc = nt*2 + (l >> 4);
                unsigned boff = (unsigned)((brow*64 + ((bc ^ (brow & 7)) << 3)) * 2);
                unsigned bh_a = (unsigned)__cvta_generic_to_shared(Bh) + boff;
                unsigned bl_a = (unsigned)__cvta_generic_to_shared(Bl) + boff;
                unsigned bh[4], bl[4];
                LDSM4T(bh, bh_a); LDSM4T(bl, bl_a);
                MMA_BF16(acc[2*nt],   ah, bh[0], bh[1]);
                MMA_BF16(acc[2*nt],   ah, bl[0], bl[1]);
                MMA_BF16(acc[2*nt],   al, bh[0], bh[1]);
                MMA_BF16(acc[2*nt+1], ah, bh[2], bh[3]);
                MMA_BF16(acc[2*nt+1], ah, bl[2], bl[3]);
                MMA_BF16(acc[2*nt+1], al, bh[2], bh[3]);
            }
        }
        __syncthreads();
    }
    const int g = l >> 2, tig = l & 3;
    const int row = crow0 + 16*w + g;
    #pragma unroll
    for (int t = 0; t < 8; t++) {
        const int col = bn + t*8 + tig*2;
        float v0 = 0.f, v1 = 0.f;
        if (isQ) { v0 = b1[col]; v1 = b1[col+1]; }
        C[(size_t)row*HD + col]       = acc[t][0] + v0;
        C[(size_t)row*HD + col+1]     = acc[t][1] + v1;
        C[(size_t)(row+8)*HD + col]   = acc[t][2] + v0;
        C[(size_t)(row+8)*HD + col+1] = acc[t][3] + v1;
    }
}

// ---------------------------------------------------------------------------
__device__ __forceinline__ float tanha(float x) {
    float y;
    asm("tanh.approx.f32 %0, %1;" : "=f"(y) : "f"(x));
    return y;
}

// ---------------------------------------------------------------------------
// Fused score + masked softmax + ant_vec.  Grid (16 q-tiles, 8 b), 512 thr.
// Warp per key; lanes span h (coalesced kv LDG, conflict-free qv/wv LDS).
// ---------------------------------------------------------------------------
__global__ void __launch_bounds__(512, 1) score_kernel(
        const float* __restrict__ c_key,
        const float* __restrict__ W2,
        float* __restrict__ out_av,
        float* __restrict__ out_ap) {
    __shared__ float qp_s[8*HD];
    __shared__ float w2_s[HD];
    __shared__ float sc_s[TK*8];
    __shared__ int   kl_s[TK];

    const int qt = blockIdx.x, b = blockIdx.y;
    const int tid = threadIdx.x;
    const int cnt = g_kcnt[b];
    const int wid = tid >> 5, lane = tid & 31;

    {
        float4* qp4 = (float4*)qp_s;
        #pragma unroll
        for (int i = tid; i < 8*HD/4; i += 512) {
            int qq = i >> 7, h4 = i & 127;
            qp4[i] = *(const float4*)(g_qp + (size_t)((qt*8 + qq)*BB + b)*HD + h4*4);
        }
        if (tid < 128) ((float4*)w2_s)[tid] = *(const float4*)(W2 + tid*4);
        if (tid < TK) kl_s[tid] = (tid < cnt) ? g_klist[b*TK + tid] : 0;
    }
    __syncthreads();

    // ---- scores: warp j handles keys ci = j, j+16, ... ----
    const float4* qp4 = (const float4*)qp_s;
    float4 wv[4];
    #pragma unroll
    for (int i = 0; i < 4; i++) wv[i] = ((const float4*)w2_s)[lane + 32*i];

    for (int ci = wid; ci < cnt; ci += 16) {
        const float4* kr = (const float4*)(g_kp + (size_t)(kl_s[ci]*BB + b)*HD);
        float acc[8] = {};
        #pragma unroll
        for (int i = 0; i < 4; i++) {
            float4 kv = kr[lane + 32*i];
            #pragma unroll
            for (int q = 0; q < 8; q++) {
                float4 qv = qp4[q*128 + lane + 32*i];
                acc[q] += tanha(kv.x+qv.x)*wv[i].x + tanha(kv.y+qv.y)*wv[i].y
                        + tanha(kv.z+qv.z)*wv[i].z + tanha(kv.w+qv.w)*wv[i].w;
            }
        }
        #pragma unroll
        for (int q = 0; q < 8; q++) {
            #pragma unroll
            for (int o = 16; o; o >>= 1)
                acc[q] += __shfl_xor_sync(0xffffffffu, acc[q], o);
        }
        if (lane == 0) {
            *(float4*)&sc_s[ci*8]     = make_float4(acc[0], acc[1], acc[2], acc[3]);
            *(float4*)&sc_s[ci*8 + 4] = make_float4(acc[4], acc[5], acc[6], acc[7]);
        }
    }
    __syncthreads();

    // ---- masked softmax over k (warps 0-7) + zero-fill masked (warps 8-15) --
    if (wid < 8) {
        const int qq = wid;
        float m = -1e30f;
        for (int ci = lane; ci < cnt; ci += 32) m = fmaxf(m, sc_s[ci*8 + qq]);
        #pragma unroll
        for (int o = 16; o; o >>= 1) m = fmaxf(m, __shfl_xor_sync(0xffffffffu, m, o));
        float s = 0.f;
        for (int ci = lane; ci < cnt; ci += 32) {
            float e = exp2f((sc_s[ci*8 + qq] - m) * 1.4426950408889634f);
            sc_s[ci*8 + qq] = e; s += e;
        }
        #pragma unroll
        for (int o = 16; o; o >>= 1) s += __shfl_xor_sync(0xffffffffu, s, o);
        const float inv = 1.0f / s;
        for (int ci = lane; ci < cnt; ci += 32) {
            float p = sc_s[ci*8 + qq] * inv;
            sc_s[ci*8 + qq] = p;
            out_ap[(size_t)kl_s[ci]*(TQ*BB) + (qt*8 + qq)*BB + b] = p;
        }
    } else {
        const int k = (wid - 8)*32 + lane;
        if (g_maskdec[b*TK + k]) {
            #pragma unroll
            for (int qq = 0; qq < 8; qq++)
                out_ap[(size_t)k*(TQ*BB) + (qt*8 + qq)*BB + b] = 0.0f;
        }
    }
    __syncthreads();

    // ---- ant_vec[q,b,h] = sum_k p[k,q] * c_key[k,b,h] ----
    const int h = tid;
    float a0=0,a1=0,a2=0,a3=0,a4=0,a5=0,a6=0,a7=0;
    #pragma unroll 8
    for (int ci = 0; ci < cnt; ci++) {
        float ck = c_key[(size_t)kl_s[ci]*(BB*HD) + b*HD + h];
        float4 p0 = *(const float4*)&sc_s[ci*8];
        float4 p1 = *(const float4*)&sc_s[ci*8 + 4];
        a0 += p0.x*ck; a1 += p0.y*ck; a2 += p0.z*ck; a3 += p0.w*ck;
        a4 += p1.x*ck; a5 += p1.y*ck; a6 += p1.z*ck; a7 += p1.w*ck;
    }
    float av[8] = {a0,a1,a2,a3,a4,a5,a6,a7};
    #pragma unroll
    for (int qq = 0; qq < 8; qq++)
        out_av[(size_t)(qt*8 + qq)*(BB*HD) + b*HD + h] = av[qq];
}

// ---------------------------------------------------------------------------
extern "C" void kernel_launch(void* const* d_in, const int* in_sizes, int n_in,
                              void* d_out, int out_size) {
    const float* query = (const float*)d_in[0];
    const float* c_key = (const float*)d_in[1];
    const void*  mask  = d_in[2];
    const float* W1    = (const float*)d_in[3];
    const float* b1    = (const float*)d_in[4];
    const float* W2    = (const float*)d_in[5];
    (void)in_sizes; (void)n_in; (void)out_size;

    float* out    = (float*)d_out;
    float* out_av = out;
    float* out_ap = out + (size_t)TQ*BB*HD;

    mask_prep<<<1, 256>>>(mask);
    convert_kernel<<<512, 256>>>(query, c_key, W1);
    proj_mma<<<dim3(8, 24), 256>>>(b1);
    score_kernel<<<dim3(TQ/8, BB), 512>>>(c_key, W2, out_av, out_ap);
}

// round 8
// speedup vs baseline: 3.0106x; 1.0352x over previous
#include <cuda_runtime.h>
#include <cuda_bf16.h>
#include <math.h>

#define TQ 128
#define TK 256
#define BB 8
#define HD 512

// rows: 0..2047 = c_key (k*8+b), 2048..3071 = query (q*8+b)
#define XROWS (TK*BB + TQ*BB)

__device__ float g_kp[TK*BB*HD];
__device__ float g_qp[TQ*BB*HD];
__device__ int   g_klist[BB*TK];
__device__ int   g_kcnt[BB];
__device__ unsigned char g_maskdec[BB*TK];
__device__ __align__(16) __nv_bfloat16 g_xh[XROWS*HD];
__device__ __align__(16) __nv_bfloat16 g_xl[XROWS*HD];
__device__ __align__(16) __nv_bfloat16 g_wh[2*HD*HD];
__device__ __align__(16) __nv_bfloat16 g_wl[2*HD*HD];

__device__ __forceinline__ unsigned pack_bf2(__nv_bfloat16 a, __nv_bfloat16 b) {
    __nv_bfloat162 t(a, b);
    return *(unsigned*)&t;
}

// ---------------------------------------------------------------------------
// mask_prep: parallel mask-dtype detect + per-b order-preserving compaction.
// ---------------------------------------------------------------------------
__global__ void __launch_bounds__(256) mask_prep(const void* __restrict__ mask) {
    __shared__ int s_isfloat, s_isbig;
    const int tid = threadIdx.x;
    if (tid == 0) { s_isfloat = 0; s_isbig = 0; }
    __syncthreads();
    for (int i = tid; i < 512; i += 256) {
        unsigned v = ((const unsigned*)mask)[i];
        if (v == 0x3f800000u) s_isfloat = 1;
        else if (v > 1u)      s_isbig = 1;
    }
    __syncthreads();
    const int mode = s_isfloat ? 2 : (s_isbig ? 1 : 0);
    const int w = tid >> 5, lane = tid & 31;
    if (w < BB) {
        const int b = w;
        int base = 0;
        #pragma unroll
        for (int c = 0; c < 8; c++) {
            const int k = c * 32 + lane;
            int mk;
            if (mode == 2)      mk = ((const float*)mask)[k*BB + b] != 0.0f;
            else if (mode == 1) mk = ((const unsigned char*)mask)[k*BB + b] != 0;
            else                mk = ((const int*)mask)[k*BB + b] != 0;
            g_maskdec[b*TK + k] = (unsigned char)mk;
            unsigned bal = __ballot_sync(0xffffffffu, !mk);
            if (!mk) {
                int pos = base + __popc(bal & ((1u << lane) - 1u));
                g_klist[b*TK + pos] = k;
            }
            base += __popc(bal);
        }
        if (lane == 0) g_kcnt[b] = base;
    }
}

// ---------------------------------------------------------------------------
// convert: pure streaming fp32 -> bf16 hi/lo split for c_key, query, W1.
// ---------------------------------------------------------------------------
__global__ void __launch_bounds__(256) convert_kernel(
        const float* __restrict__ query,
        const float* __restrict__ c_key,
        const float* __restrict__ W1) {
    const int NCK = (TK*BB*HD)/4;
    const int NQ  = (TQ*BB*HD)/4;
    const int NW  = (2*HD*HD)/4;
    const int total = NCK + NQ + NW;
    const int stride = gridDim.x * blockDim.x;
    for (int i = blockIdx.x*blockDim.x + threadIdx.x; i < total; i += stride) {
        const float4* src; __nv_bfloat16 *H, *L; int e;
        if (i < NCK)          { src = (const float4*)c_key + i;       e = i*4;                  H = g_xh; L = g_xl; }
        else if (i < NCK+NQ)  { src = (const float4*)query + (i-NCK); e = (i-NCK)*4 + TK*BB*HD; H = g_xh; L = g_xl; }
        else                  { src = (const float4*)W1 + (i-NCK-NQ); e = (i-NCK-NQ)*4;         H = g_wh; L = g_wl; }
        float4 v = *src;
        __nv_bfloat16 hx = __float2bfloat16(v.x), hy = __float2bfloat16(v.y);
        __nv_bfloat16 hz = __float2bfloat16(v.z), hw = __float2bfloat16(v.w);
        __nv_bfloat16 lx = __float2bfloat16(v.x - __bfloat162float(hx));
        __nv_bfloat16 ly = __float2bfloat16(v.y - __bfloat162float(hy));
        __nv_bfloat16 lz = __float2bfloat16(v.z - __bfloat162float(hz));
        __nv_bfloat16 lw = __float2bfloat16(v.w - __bfloat162float(hw));
        uint2 hp = make_uint2(pack_bf2(hx,hy), pack_bf2(hz,hw));
        uint2 lp = make_uint2(pack_bf2(lx,ly), pack_bf2(lz,lw));
        *(uint2*)&H[e] = hp;
        *(uint2*)&L[e] = lp;
    }
}

// ---------------------------------------------------------------------------
// Projection GEMM (bf16 hi/lo split, 3 MMA products).  128x64 tile, 256 thr.
// ---------------------------------------------------------------------------
#define LDSM4(R, addr) \
    asm volatile("ldmatrix.sync.aligned.m8n8.x4.shared.b16 {%0,%1,%2,%3}, [%4];" \
        : "=r"(R[0]),"=r"(R[1]),"=r"(R[2]),"=r"(R[3]) : "r"(addr))
#define LDSM4T(R, addr) \
    asm volatile("ldmatrix.sync.aligned.m8n8.x4.trans.shared.b16 {%0,%1,%2,%3}, [%4];" \
        : "=r"(R[0]),"=r"(R[1]),"=r"(R[2]),"=r"(R[3]) : "r"(addr))
#define MMA_BF16(C, A, B0, B1) \
    asm volatile("mma.sync.aligned.m16n8k16.row.col.f32.bf16.bf16.f32 " \
        "{%0,%1,%2,%3},{%4,%5,%6,%7},{%8,%9},{%0,%1,%2,%3};" \
        : "+f"(C[0]),"+f"(C[1]),"+f"(C[2]),"+f"(C[3]) \
        : "r"(A[0]),"r"(A[1]),"r"(A[2]),"r"(A[3]), "r"(B0),"r"(B1))

__global__ void __launch_bounds__(256) proj_mma(const float* __restrict__ b1) {
    __shared__ __align__(16) __nv_bfloat16 Ah[128*64], Al[128*64];
    __shared__ __align__(16) __nv_bfloat16 Bh[64*64],  Bl[64*64];
    const int tid = threadIdx.x, w = tid >> 5, l = tid & 31;
    const int by = blockIdx.y, bn = blockIdx.x * 64;
    const int isQ = (by >= 16);
    const int xrow0 = isQ ? (TK*BB + (by-16)*128) : by*128;
    const int wrow0 = isQ ? HD : 0;
    float* C = isQ ? g_qp : g_kp;
    const int crow0 = isQ ? (by-16)*128 : by*128;
    float acc[8][4] = {};

    for (int kc = 0; kc < HD; kc += 64) {
        #pragma unroll
        for (int t = 0; t < 4; t++) {
            int idx = tid + t*256;
            int r = idx >> 3, c = idx & 7;
            int so = r*64 + ((c ^ (r & 7)) << 3);
            size_t ge = (size_t)(xrow0 + r)*HD + kc + c*8;
            *(uint4*)&Ah[so] = *(const uint4*)&g_xh[ge];
            *(uint4*)&Al[so] = *(const uint4*)&g_xl[ge];
        }
        #pragma unroll
        for (int t = 0; t < 2; t++) {
            int idx = tid + t*256;
            int r = idx >> 3, c = idx & 7;
            int so = r*64 + ((c ^ (r & 7)) << 3);
            size_t ge = (size_t)(wrow0 + kc + r)*HD + bn + c*8;
            *(uint4*)&Bh[so] = *(const uint4*)&g_wh[ge];
            *(uint4*)&Bl[so] = *(const uint4*)&g_wl[ge];
        }
        __syncthreads();
        #pragma unroll
        for (int ks = 0; ks < 4; ks++) {
            int arow = 16*w + (l & 15);
            int ac = ks*2 + (l >> 4);
            unsigned aoff = (unsigned)((arow*64 + ((ac ^ (arow & 7)) << 3)) * 2);
            unsigned ah_a = (unsigned)__cvta_generic_to_shared(Ah) + aoff;
            unsigned al_a = (unsigned)__cvta_generic_to_shared(Al) + aoff;
            unsigned ah[4], al[4];
            LDSM4(ah, ah_a); LDSM4(al, al_a);
            #pragma unroll
            for (int nt = 0; nt < 4; nt++) {
                int brow = ks*16 + (l & 15);
                int bc = nt*2 + (l >> 4);
                unsigned boff = (unsigned)((brow*64 + ((bc ^ (brow & 7)) << 3)) * 2);
                unsigned bh_a = (unsigned)__cvta_generic_to_shared(Bh) + boff;
                unsigned bl_a = (unsigned)__cvta_generic_to_shared(Bl) + boff;
                unsigned bh[4], bl[4];
                LDSM4T(bh, bh_a); LDSM4T(bl, bl_a);
                MMA_BF16(acc[2*nt],   ah, bh[0], bh[1]);
                MMA_BF16(acc[2*nt],   ah, bl[0], bl[1]);
                MMA_BF16(acc[2*nt],   al, bh[0], bh[1]);
                MMA_BF16(acc[2*nt+1], ah, bh[2], bh[3]);
                MMA_BF16(acc[2*nt+1], ah, bl[2], bl[3]);
                MMA_BF16(acc[2*nt+1], al, bh[2], bh[3]);
            }
        }
        __syncthreads();
    }
    const int g = l >> 2, tig = l & 3;
    const int row = crow0 + 16*w + g;
    #pragma unroll
    for (int t = 0; t < 8; t++) {
        const int col = bn + t*8 + tig*2;
        float v0 = 0.f, v1 = 0.f;
        if (isQ) { v0 = b1[col]; v1 = b1[col+1]; }
        C[(size_t)row*HD + col]       = acc[t][0] + v0;
        C[(size_t)row*HD + col+1]     = acc[t][1] + v1;
        C[(size_t)(row+8)*HD + col]   = acc[t][2] + v0;
        C[(size_t)(row+8)*HD + col+1] = acc[t][3] + v1;
    }
}

// ---------------------------------------------------------------------------
__device__ __forceinline__ float tanha(float x) {
    float y;
    asm("tanh.approx.f32 %0, %1;" : "=f"(y) : "f"(x));
    return y;
}

// ---------------------------------------------------------------------------
// Fused score + masked softmax + ant_vec.
// q-tile = 4.  Grid (32 q-tiles, 8 b) = 256 blocks; 512 thr; 2 blocks/SM.
// Warp per key; lanes span h (coalesced kv LDG, conflict-free qv/wv LDS).
// ---------------------------------------------------------------------------
#define QT 4
__global__ void __launch_bounds__(512, 2) score_kernel(
        const float* __restrict__ c_key,
        const float* __restrict__ W2,
        float* __restrict__ out_av,
        float* __restrict__ out_ap) {
    __shared__ float qp_s[QT*HD];
    __shared__ float w2_s[HD];
    __shared__ float sc_s[TK*QT];
    __shared__ int   kl_s[TK];

    const int qt = blockIdx.x, b = blockIdx.y;
    const int tid = threadIdx.x;
    const int cnt = g_kcnt[b];
    const int wid = tid >> 5, lane = tid & 31;

    {
        float4* qp4 = (float4*)qp_s;
        #pragma unroll
        for (int i = tid; i < QT*HD/4; i += 512) {
            int qq = i >> 7, h4 = i & 127;
            qp4[i] = *(const float4*)(g_qp + (size_t)((qt*QT + qq)*BB + b)*HD + h4*4);
        }
        if (tid < 128) ((float4*)w2_s)[tid] = *(const float4*)(W2 + tid*4);
        if (tid < TK) kl_s[tid] = (tid < cnt) ? g_klist[b*TK + tid] : 0;
    }
    __syncthreads();

    // ---- scores: warp j handles keys ci = j, j+16, ... ----
    const float4* qp4 = (const float4*)qp_s;
    float4 wv[4];
    #pragma unroll
    for (int i = 0; i < 4; i++) wv[i] = ((const float4*)w2_s)[lane + 32*i];

    for (int ci = wid; ci < cnt; ci += 16) {
        const float4* kr = (const float4*)(g_kp + (size_t)(kl_s[ci]*BB + b)*HD);
        float acc[QT] = {};
        #pragma unroll
        for (int i = 0; i < 4; i++) {
            float4 kv = kr[lane + 32*i];
            #pragma unroll
            for (int q = 0; q < QT; q++) {
                float4 qv = qp4[q*128 + lane + 32*i];
                acc[q] += tanha(kv.x+qv.x)*wv[i].x + tanha(kv.y+qv.y)*wv[i].y
                        + tanha(kv.z+qv.z)*wv[i].z + tanha(kv.w+qv.w)*wv[i].w;
            }
        }
        #pragma unroll
        for (int q = 0; q < QT; q++) {
            #pragma unroll
            for (int o = 16; o; o >>= 1)
                acc[q] += __shfl_xor_sync(0xffffffffu, acc[q], o);
        }
        if (lane == 0)
            *(float4*)&sc_s[ci*QT] = make_float4(acc[0], acc[1], acc[2], acc[3]);
    }
    __syncthreads();

    // ---- masked softmax over k (warps 0-3) + zero-fill masked (warps 4-11) --
    if (wid < QT) {
        const int qq = wid;
        float m = -1e30f;
        for (int ci = lane; ci < cnt; ci += 32) m = fmaxf(m, sc_s[ci*QT + qq]);
        #pragma unroll
        for (int o = 16; o; o >>= 1) m = fmaxf(m, __shfl_xor_sync(0xffffffffu, m, o));
        float s = 0.f;
        for (int ci = lane; ci < cnt; ci += 32) {
            float e = exp2f((sc_s[ci*QT + qq] - m) * 1.4426950408889634f);
            sc_s[ci*QT + qq] = e; s += e;
        }
        #pragma unroll
        for (int o = 16; o; o >>= 1) s += __shfl_xor_sync(0xffffffffu, s, o);
        const float inv = 1.0f / s;
        for (int ci = lane; ci < cnt; ci += 32) {
            float p = sc_s[ci*QT + qq] * inv;
            sc_s[ci*QT + qq] = p;
            out_ap[(size_t)kl_s[ci]*(TQ*BB) + (qt*QT + qq)*BB + b] = p;
        }
    } else if (wid < QT + 8) {
        const int k = (wid - QT)*32 + lane;
        if (g_maskdec[b*TK + k]) {
            #pragma unroll
            for (int qq = 0; qq < QT; qq++)
                out_ap[(size_t)k*(TQ*BB) + (qt*QT + qq)*BB + b] = 0.0f;
        }
    }
    __syncthreads();

    // ---- ant_vec[q,b,h] = sum_k p[k,q] * c_key[k,b,h] ----
    const int h = tid;
    float a0=0,a1=0,a2=0,a3=0;
    #pragma unroll 8
    for (int ci = 0; ci < cnt; ci++) {
        float ck = c_key[(size_t)kl_s[ci]*(BB*HD) + b*HD + h];
        float4 p = *(const float4*)&sc_s[ci*QT];
        a0 += p.x*ck; a1 += p.y*ck; a2 += p.z*ck; a3 += p.w*ck;
    }
    float av[QT] = {a0,a1,a2,a3};
    #pragma unroll
    for (int qq = 0; qq < QT; qq++)
        out_av[(size_t)(qt*QT + qq)*(BB*HD) + b*HD + h] = av[qq];
}

// ---------------------------------------------------------------------------
extern "C" void kernel_launch(void* const* d_in, const int* in_sizes, int n_in,
                              void* d_out, int out_size) {
    const float* query = (const float*)d_in[0];
    const float* c_key = (const float*)d_in[1];
    const void*  mask  = d_in[2];
    const float* W1    = (const float*)d_in[3];
    const float* b1    = (const float*)d_in[4];
    const float* W2    = (const float*)d_in[5];
    (void)in_sizes; (void)n_in; (void)out_size;

    float* out    = (float*)d_out;
    float* out_av = out;
    float* out_ap = out + (size_t)TQ*BB*HD;

    mask_prep<<<1, 256>>>(mask);
    convert_kernel<<<512, 256>>>(query, c_key, W1);
    proj_mma<<<dim3(8, 24), 256>>>(b1);
    score_kernel<<<dim3(TQ/QT, BB), 512>>>(c_key, W2, out_av, out_ap);
}